// round 6
// baseline (speedup 1.0000x reference)
#include <cuda_runtime.h>
#include <cuda_bf16.h>
#include <math.h>
#include <stdint.h>

#define TOKENS 288
#define DM 512
#define NE 16
#define KTOP 4
#define NPAIR (3*TOKENS*KTOP)
#define LCAP 1024
#define HID 2048

// ---------------- scratch ----------------
__device__ float g_views[3*TOKENS*DM];
__device__ float g_pw[NPAIR];
__device__ int   g_counts[NE];
__device__ int   g_lists[NE*LCAP];
__device__ __nv_bfloat16 g_vb[(size_t)3*TOKENS*3*DM];        // views, interleaved A-pattern (hi,hi,lo)
__device__ __nv_bfloat16 g_w1i[(size_t)NE*HID*3*DM];         // W1^T interleaved B-pattern (hi,lo,hi)
__device__ __nv_bfloat16 g_w2i[(size_t)NE*DM*3*HID];         // W2^T interleaved B-pattern
__device__ __nv_bfloat16 g_hb[(size_t)NPAIR*3*HID];          // gelu(h), interleaved A-pattern
__device__ float g_y[(size_t)NPAIR*DM];
__device__ float g_part[(size_t)16*TOKENS*HID];
__device__ float g_x[TOKENS*DM];
__device__ float g_attno[TOKENS*DM];
__device__ float g_hid[TOKENS*HID];

__global__ void zero_kernel() { if (threadIdx.x < NE) g_counts[threadIdx.x] = 0; }

// ---------------- f32x2 helpers (dense path) ----------------
__device__ __forceinline__ unsigned long long dup2(float a) {
    unsigned long long r; asm("mov.b64 %0, {%1,%1};" : "=l"(r) : "f"(a)); return r;
}
__device__ __forceinline__ unsigned long long fma2(unsigned long long a, unsigned long long b,
                                                   unsigned long long c) {
    unsigned long long d; asm("fma.rn.f32x2 %0, %1, %2, %3;" : "=l"(d) : "l"(a), "l"(b), "l"(c)); return d;
}
__device__ __forceinline__ void unpack2(unsigned long long v, float& lo, float& hi) {
    asm("mov.b64 {%0,%1}, %2;" : "=f"(lo), "=f"(hi) : "l"(v));
}

// ---------------- bf16 helpers ----------------
__device__ __forceinline__ unsigned short bfbits(__nv_bfloat16 h) {
    return *reinterpret_cast<unsigned short*>(&h);
}

// ---------------- MoE grouped GEMM via mma.sync (HMMA bf16) ----------------
// Block: 128 M x 64 N, 256 thr (8 warps x 16 rows). K consumed in 32-bf16 chunks.
// MODE 1 (up):  A=g_vb row slot>>2, B=g_w1i, out=g_hb bf16 triplets, bias+gelu
// MODE 2 (down):A=g_hb row slot,    B=g_w2i, out=g_y fp32, bias
template<int MODE, int NC, int KB, int NTOT>
__global__ void __launch_bounds__(256) moe_mma_kernel(
    const __nv_bfloat16* __restrict__ Asrc, const __nv_bfloat16* __restrict__ Bsrc,
    const float* __restrict__ bias, float* __restrict__ OutF, __nv_bfloat16* __restrict__ OutB)
{
    __shared__ int rs[128];
    __shared__ __nv_bfloat16 As[2][128][40];   // 32 data + 8 pad
    __shared__ __nv_bfloat16 Bs[2][64][40];

    int e = blockIdx.z;
    int Mcur = g_counts[e];
    int mBase = blockIdx.y * 128;
    if (mBase >= Mcur) return;
    int nBase = blockIdx.x * 64;
    int tid = threadIdx.x, wid = tid >> 5, lane = tid & 31;

    if (tid < 128) {
        int gm = mBase + tid;
        rs[tid] = (gm < Mcur) ? g_lists[e*LCAP + gm] : g_lists[e*LCAP];
    }
    __syncthreads();

    // per-thread staging coords
    const int arow_l = tid >> 1, aq = (tid & 1) * 16;   // A: 128 rows x 32 bf16 (2 uint4/thr)
    const int brow_l = tid >> 2, bq = (tid & 3) * 8;    // B: 64 rows x 32 bf16 (1 uint4/thr)

    const __nv_bfloat16* aPtr;
    {
        int slot = rs[arow_l];
        int sr = (MODE == 1) ? (slot >> 2) : slot;
        aPtr = Asrc + (size_t)sr * KB;
    }
    const __nv_bfloat16* bPtr = Bsrc + (size_t)e * NTOT * KB + (size_t)(nBase + brow_l) * KB;
    bias += (size_t)e * NTOT;

    float acc[8][4];
    #pragma unroll
    for (int i = 0; i < 8; i++)
        #pragma unroll
        for (int j = 0; j < 4; j++) acc[i][j] = 0.f;

    const int wm = wid * 16;
    const int fr = lane >> 2, fc = (lane & 3) * 2;

    // prologue: chunk 0
    uint4 pa0 = *(const uint4*)(aPtr + aq);
    uint4 pa1 = *(const uint4*)(aPtr + aq + 8);
    uint4 pb0 = *(const uint4*)(bPtr + bq);
    *(uint4*)&As[0][arow_l][aq]     = pa0;
    *(uint4*)&As[0][arow_l][aq + 8] = pa1;
    *(uint4*)&Bs[0][brow_l][bq]     = pb0;
    __syncthreads();

    int p = 0;
    for (int ci = 0; ci < NC; ci++) {
        const bool more = (ci + 1) < NC;
        if (more) {
            pa0 = *(const uint4*)(aPtr + (ci+1)*32 + aq);
            pa1 = *(const uint4*)(aPtr + (ci+1)*32 + aq + 8);
            pb0 = *(const uint4*)(bPtr + (ci+1)*32 + bq);
        }
        #pragma unroll
        for (int ks = 0; ks < 2; ks++) {
            const int kb = ks * 16;
            uint32_t a0 = *(const uint32_t*)&As[p][wm + fr    ][kb + fc];
            uint32_t a1 = *(const uint32_t*)&As[p][wm + fr + 8][kb + fc];
            uint32_t a2 = *(const uint32_t*)&As[p][wm + fr    ][kb + fc + 8];
            uint32_t a3 = *(const uint32_t*)&As[p][wm + fr + 8][kb + fc + 8];
            #pragma unroll
            for (int nt = 0; nt < 8; nt++) {
                uint32_t b0 = *(const uint32_t*)&Bs[p][nt*8 + fr][kb + fc];
                uint32_t b1 = *(const uint32_t*)&Bs[p][nt*8 + fr][kb + fc + 8];
                asm volatile(
                    "mma.sync.aligned.m16n8k16.row.col.f32.bf16.bf16.f32 "
                    "{%0,%1,%2,%3}, {%4,%5,%6,%7}, {%8,%9}, {%0,%1,%2,%3};"
                    : "+f"(acc[nt][0]), "+f"(acc[nt][1]), "+f"(acc[nt][2]), "+f"(acc[nt][3])
                    : "r"(a0), "r"(a1), "r"(a2), "r"(a3), "r"(b0), "r"(b1));
            }
        }
        if (more) {
            int q = p ^ 1;
            *(uint4*)&As[q][arow_l][aq]     = pa0;
            *(uint4*)&As[q][arow_l][aq + 8] = pa1;
            *(uint4*)&Bs[q][brow_l][bq]     = pb0;
            __syncthreads();
            p = q;
        }
    }

    // epilogue: acc[nt][0..1] -> row wm+fr, cols fc..fc+1; acc[nt][2..3] -> row wm+fr+8
    #pragma unroll
    for (int half = 0; half < 2; half++) {
        int mloc = wm + fr + half*8;
        if (mBase + mloc >= Mcur) continue;
        int slot = rs[mloc];
        #pragma unroll
        for (int nt = 0; nt < 8; nt++) {
            int n = nBase + nt*8 + fc;
            float v0 = acc[nt][half*2 + 0] + bias[n];
            float v1 = acc[nt][half*2 + 1] + bias[n + 1];
            if (MODE == 1) {
                v0 = 0.5f*v0*(1.f + erff(v0*0.7071067811865476f));
                v1 = 0.5f*v1*(1.f + erff(v1*0.7071067811865476f));
                __nv_bfloat16 h0 = __float2bfloat16(v0);
                __nv_bfloat16 l0 = __float2bfloat16(v0 - __bfloat162float(h0));
                __nv_bfloat16 h1 = __float2bfloat16(v1);
                __nv_bfloat16 l1 = __float2bfloat16(v1 - __bfloat162float(h1));
                uint32_t w0 = (uint32_t)bfbits(h0) | ((uint32_t)bfbits(h0) << 16);
                uint32_t w1 = (uint32_t)bfbits(l0) | ((uint32_t)bfbits(h1) << 16);
                uint32_t w2 = (uint32_t)bfbits(h1) | ((uint32_t)bfbits(l1) << 16);
                uint32_t* dst = (uint32_t*)(OutB + (size_t)slot*(3*HID) + 3*n);
                dst[0] = w0; dst[1] = w1; dst[2] = w2;
            } else {
                *(float2*)(OutF + (size_t)slot*DM + n) = make_float2(v0, v1);
            }
        }
    }
}

// ---------------- weight prep: W[e][K][N] -> out[e][n][3K bf16], B-pattern (hi,lo,hi) ----
__global__ void iw_kernel(const float* __restrict__ in, __nv_bfloat16* __restrict__ out, int K, int N)
{
    __shared__ float t[32][33];
    int e = blockIdx.z;
    in  += (size_t)e * K * N;
    out += (size_t)e * N * 3 * K;
    int n0 = blockIdx.x * 32, k0 = blockIdx.y * 32;
    int tid = threadIdx.x;            // 128
    int tx = tid & 31, r0 = tid >> 5;
    #pragma unroll
    for (int i = 0; i < 32; i += 4)
        t[i + r0][tx] = in[(size_t)(k0 + i + r0) * N + n0 + tx];
    __syncthreads();
    int nl = tid >> 2, g = tid & 3;
    __align__(16) __nv_bfloat16 tmp[24];
    #pragma unroll
    for (int j = 0; j < 8; j++) {
        float v = t[g*8 + j][nl];
        __nv_bfloat16 h = __float2bfloat16(v);
        __nv_bfloat16 l = __float2bfloat16(v - __bfloat162float(h));
        tmp[3*j] = h; tmp[3*j+1] = l; tmp[3*j+2] = h;
    }
    uint4* dst = (uint4*)(out + (size_t)(n0 + nl) * 3 * K + (size_t)3 * (k0 + g*8));
    const uint4* s4 = (const uint4*)tmp;
    dst[0] = s4[0]; dst[1] = s4[1]; dst[2] = s4[2];
}

// ---------------- views prep: g_views -> g_vb, A-pattern (hi,hi,lo) ----------------
__global__ void iv_kernel()
{
    int row = blockIdx.x, tid = threadIdx.x;   // 64 threads x 8 el
    const float* src = g_views + (size_t)row * DM + tid * 8;
    __align__(16) __nv_bfloat16 tmp[24];
    #pragma unroll
    for (int j = 0; j < 8; j++) {
        float v = src[j];
        __nv_bfloat16 h = __float2bfloat16(v);
        __nv_bfloat16 l = __float2bfloat16(v - __bfloat162float(h));
        tmp[3*j] = h; tmp[3*j+1] = h; tmp[3*j+2] = l;
    }
    uint4* dst = (uint4*)(g_vb + (size_t)row * (3*DM) + tid * 24);
    const uint4* s4 = (const uint4*)tmp;
    dst[0] = s4[0]; dst[1] = s4[1]; dst[2] = s4[2];
}

// ---------------- embedding ----------------
__global__ void embed_kernel(const int* __restrict__ Z,
    const float* __restrict__ e0, const float* __restrict__ p0, const float* __restrict__ b0,
    const float* __restrict__ e1, const float* __restrict__ p1, const float* __restrict__ b1,
    const float* __restrict__ e2, const float* __restrict__ p2, const float* __restrict__ b2)
{
    int t = blockIdx.x, view = blockIdx.y;
    const float *emb, *pw, *pb; int F;
    if (view == 0)      { emb = e0; pw = p0; pb = b0; F = 200; }
    else if (view == 1) { emb = e1; pw = p1; pb = b1; F = 132; }
    else                { emb = e2; pw = p2; pb = b2; F = 112; }
    __shared__ float er[200];
    int z = Z[t];
    for (int f = threadIdx.x; f < F; f += blockDim.x) er[f] = emb[z*F + f];
    __syncthreads();
    for (int d = threadIdx.x; d < DM; d += blockDim.x) {
        float acc = pb[d];
        for (int f = 0; f < F; f++) acc = fmaf(er[f], pw[f*DM + d], acc);
        g_views[(view*TOKENS + t)*DM + d] = acc;
    }
}

// ---------------- routing ----------------
__global__ void route_kernel(const float* __restrict__ keys, const float* __restrict__ rw,
                             const float* __restrict__ rb)
{
    int t = blockIdx.x, view = blockIdx.y;
    const float* v = &g_views[(view*TOKENS + t)*DM];
    __shared__ float vs[DM];
    __shared__ float logits[NE];
    for (int d = threadIdx.x; d < DM; d += blockDim.x) vs[d] = v[d];
    __syncthreads();
    int warp = threadIdx.x >> 5, lane = threadIdx.x & 31;
    for (int e = warp; e < NE; e += 8) {
        float a = 0.f, b = 0.f;
        for (int d = lane; d < DM; d += 32) {
            float kk = keys[e*DM + d];
            a = fmaf(vs[d], 2.f*kk + rw[(view*DM + d)*NE + e], a);
            b = fmaf(kk, kk, b);
        }
        #pragma unroll
        for (int o = 16; o; o >>= 1) {
            a += __shfl_down_sync(0xffffffffu, a, o);
            b += __shfl_down_sync(0xffffffffu, b, o);
        }
        if (lane == 0) logits[e] = a - b + rb[view*NE + e];
    }
    __syncthreads();
    if (threadIdx.x == 0) {
        float vals[KTOP]; int idx[KTOP]; bool used[NE];
        for (int e = 0; e < NE; e++) used[e] = false;
        for (int k = 0; k < KTOP; k++) {
            float best = -1e30f; int bi = 0;
            for (int e = 0; e < NE; e++)
                if (!used[e] && logits[e] > best) { best = logits[e]; bi = e; }
            used[bi] = true; vals[k] = best; idx[k] = bi;
        }
        float m = vals[0], s = 0.f, w[KTOP];
        for (int k = 0; k < KTOP; k++) { w[k] = expf(vals[k] - m); s += w[k]; }
        float inv = 1.f / s;
        for (int k = 0; k < KTOP; k++) {
            int slot = (view*TOKENS + t)*KTOP + k;
            g_pw[slot] = w[k] * inv;
            int pos = atomicAdd(&g_counts[idx[k]], 1);
            if (pos < LCAP) g_lists[idx[k]*LCAP + pos] = slot;
        }
    }
}

// ---------------- dense GEMM (split-K, f32x2, 128x128x16) ----------------
template<int SPLITS>
__global__ void __launch_bounds__(256, 2) dgemm_kernel(
    const float* __restrict__ A, const float* __restrict__ W, float* __restrict__ C,
    int M, int N, int K)
{
    int s = blockIdx.z;
    int nBase = blockIdx.x * 128, mBase = blockIdx.y * 128;
    __shared__ float As[16][136];
    __shared__ float Bs[16][128];
    const int tid = threadIdx.x;
    const int tr = tid >> 4, tc = tid & 15;
    const int lr = tid >> 1, lkq = (tid & 1) * 8;
    const int wr = tid >> 4, wc = (tid & 15) * 8;
    const int kChunk = K / SPLITS, kStart = s * kChunk, kEnd = kStart + kChunk;
    int gm = mBase + lr;
    bool rv = gm < M;
    const float* Arow = A + (size_t)(rv ? gm : 0) * K;
    const float* Wp = W + nBase + wc;

    unsigned long long acc[8][4];
    #pragma unroll
    for (int i = 0; i < 8; i++)
        #pragma unroll
        for (int j = 0; j < 4; j++) acc[i][j] = 0ull;

    for (int k0 = kStart; k0 < kEnd; k0 += 16) {
        float4 a0 = rv ? *(const float4*)(Arow + k0 + lkq)     : make_float4(0,0,0,0);
        float4 a1 = rv ? *(const float4*)(Arow + k0 + lkq + 4) : make_float4(0,0,0,0);
        As[lkq+0][lr]=a0.x; As[lkq+1][lr]=a0.y; As[lkq+2][lr]=a0.z; As[lkq+3][lr]=a0.w;
        As[lkq+4][lr]=a1.x; As[lkq+5][lr]=a1.y; As[lkq+6][lr]=a1.z; As[lkq+7][lr]=a1.w;
        const float* wp = Wp + (size_t)(k0 + wr) * N;
        *(float4*)(&Bs[wr][wc])     = *(const float4*)(wp);
        *(float4*)(&Bs[wr][wc + 4]) = *(const float4*)(wp + 4);
        __syncthreads();
        #pragma unroll
        for (int k = 0; k < 16; k++) {
            float4 aA = *(const float4*)(&As[k][tr*4]);
            float4 aB = *(const float4*)(&As[k][64 + tr*4]);
            ulonglong2 c0 = *(const ulonglong2*)(&Bs[k][tc*4]);
            ulonglong2 c1 = *(const ulonglong2*)(&Bs[k][64 + tc*4]);
            unsigned long long da[8];
            da[0]=dup2(aA.x); da[1]=dup2(aA.y); da[2]=dup2(aA.z); da[3]=dup2(aA.w);
            da[4]=dup2(aB.x); da[5]=dup2(aB.y); da[6]=dup2(aB.z); da[7]=dup2(aB.w);
            #pragma unroll
            for (int i = 0; i < 8; i++) {
                acc[i][0] = fma2(da[i], c0.x, acc[i][0]);
                acc[i][1] = fma2(da[i], c0.y, acc[i][1]);
                acc[i][2] = fma2(da[i], c1.x, acc[i][2]);
                acc[i][3] = fma2(da[i], c1.y, acc[i][3]);
            }
        }
        __syncthreads();
    }
    #pragma unroll
    for (int i = 0; i < 8; i++) {
        int mloc = (i < 4) ? (tr*4 + i) : (64 + tr*4 + (i - 4));
        int m = mBase + mloc;
        if (m >= M) continue;
        size_t crow = ((size_t)s * M + m) * N;
        #pragma unroll
        for (int j = 0; j < 4; j++) {
            int n = nBase + ((j < 2) ? (tc*4 + j*2) : (64 + tc*4 + (j - 2)*2));
            float lo, hi; unpack2(acc[i][j], lo, hi);
            *(float2*)(C + crow + n) = make_float2(lo, hi);
        }
    }
}

// ---------------- split-K reduce + bias (+relu) ----------------
template<int ACT>
__global__ void reduce_bias_kernel(const float* __restrict__ part, const float* __restrict__ bias,
                                   float* __restrict__ out, int M, int N, int S)
{
    int idx = blockIdx.x * 256 + threadIdx.x;
    if (idx >= M * N) return;
    int n = idx % N;
    float acc = bias[n];
    for (int s = 0; s < S; s++) acc += part[(size_t)s * M * N + idx];
    if (ACT == 2) acc = fmaxf(acc, 0.f);
    out[idx] = acc;
}

// ---------------- MoE combine + fractional positional encoding ----------------
__global__ void combine_kernel(const float* __restrict__ frac)
{
    int t = blockIdx.x, d = threadIdx.x;
    float acc = 0.f;
    #pragma unroll
    for (int view = 0; view < 3; view++)
        #pragma unroll
        for (int k = 0; k < KTOP; k++) {
            int slot = (view*TOKENS + t)*KTOP + k;
            acc = fmaf(g_pw[slot], g_y[(size_t)slot*DM + d], acc);
        }
    float fr = frac[t];
    int j; float r;
    if (d < 256) { j = d; r = fr; }
    else {
        j = d - 256;
        float l = log2f(fr);
        r = fminf(0.0025f * l * l, 1.0f);
    }
    r = fmaxf(r, 0.0002f);
    int idx = (int)rintf(r * 5000.0f) - 1;
    idx = max(0, min(4999, idx));
    double dv  = pow(50.0, (double)(2*j) / 256.0);
    float pe = (float)((j & 1) ? cos((double)idx / dv) : sin((double)idx / dv));
    g_x[t*DM + d] = acc + pe;
}

// ---------------- attention (folds qkv split-K reduce + bias) ----------------
__global__ void attn_kernel(const float* __restrict__ part, const float* __restrict__ qb)
{
    int b = blockIdx.x, h = blockIdx.y;
    __shared__ float q[9][64], k[9][64], v[9][64], s[9][9];
    for (int i = threadIdx.x; i < 9*64; i += blockDim.x) {
        int l = i >> 6, d = i & 63;
        size_t row = (size_t)(b*9 + l)*1536 + h*64 + d;
        float qq = qb[h*64 + d], kk = qb[512 + h*64 + d], vv = qb[1024 + h*64 + d];
        #pragma unroll
        for (int sp = 0; sp < 4; sp++) {
            size_t o = (size_t)sp*TOKENS*1536 + row;
            qq += part[o]; kk += part[o + 512]; vv += part[o + 1024];
        }
        q[l][d] = qq; k[l][d] = kk; v[l][d] = vv;
    }
    __syncthreads();
    for (int i = threadIdx.x; i < 81; i += blockDim.x) {
        int qi = i / 9, kj = i % 9; float a = 0.f;
        #pragma unroll
        for (int d = 0; d < 64; d++) a = fmaf(q[qi][d], k[kj][d], a);
        s[qi][kj] = a * 0.125f;
    }
    __syncthreads();
    if (threadIdx.x < 9) {
        int i = threadIdx.x;
        float m = s[i][0];
        for (int jj = 1; jj < 9; jj++) m = fmaxf(m, s[i][jj]);
        float sum = 0.f;
        for (int jj = 0; jj < 9; jj++) { float ee = expf(s[i][jj] - m); s[i][jj] = ee; sum += ee; }
        float inv = 1.f / sum;
        for (int jj = 0; jj < 9; jj++) s[i][jj] *= inv;
    }
    __syncthreads();
    for (int i = threadIdx.x; i < 9*64; i += blockDim.x) {
        int l = i >> 6, d = i & 63; float a = 0.f;
        #pragma unroll
        for (int jj = 0; jj < 9; jj++) a = fmaf(s[l][jj], v[jj][d], a);
        g_attno[(size_t)(b*9 + l)*DM + h*64 + d] = a;
    }
}

// ---------------- split-K reduce + residual + LayerNorm ----------------
__device__ __forceinline__ float blockSum(float v, float* red)
{
    int lane = threadIdx.x & 31, w = threadIdx.x >> 5;
    #pragma unroll
    for (int o = 16; o; o >>= 1) v += __shfl_down_sync(0xffffffffu, v, o);
    if (lane == 0) red[w] = v;
    __syncthreads();
    if (threadIdx.x == 0) { float ss = 0.f; for (int i = 0; i < 8; i++) ss += red[i]; red[0] = ss; }
    __syncthreads();
    float r = red[0];
    __syncthreads();
    return r;
}

__global__ void reduce_addln_kernel(const float* __restrict__ part, int S,
                                    const float* __restrict__ bias,
                                    const float* __restrict__ gam, const float* __restrict__ bet)
{
    int t = blockIdx.x, tid = threadIdx.x;
    __shared__ float red[8];
    float y0 = bias[tid], y1 = bias[tid + 256];
    for (int s = 0; s < S; s++) {
        y0 += part[((size_t)s*TOKENS + t)*DM + tid];
        y1 += part[((size_t)s*TOKENS + t)*DM + tid + 256];
    }
    float s0 = g_x[t*DM + tid] + y0;
    float s1 = g_x[t*DM + tid + 256] + y1;
    float mean = blockSum(s0 + s1, red) * (1.f/512.f);
    float d0 = s0 - mean, d1 = s1 - mean;
    float var = blockSum(d0*d0 + d1*d1, red) * (1.f/512.f);
    float inv = rsqrtf(var + 1e-5f);
    g_x[t*DM + tid]       = d0*inv*gam[tid]       + bet[tid];
    g_x[t*DM + tid + 256] = d1*inv*gam[tid + 256] + bet[tid + 256];
}

__global__ void finalize_kernel(const float* __restrict__ frac, float* __restrict__ out)
{
    int t = blockIdx.x, d = threadIdx.x;
    out[t*DM + d] = g_x[t*DM + d] * frac[t];
}

// ---------------------------------- host ----------------------------------
extern "C" void kernel_launch(void* const* d_in, const int* in_sizes, int n_in,
                              void* d_out, int out_size)
{
    const int*   Z    = (const int*)d_in[0];
    const float* frac = (const float*)d_in[1];
    const float *emb0, *p0w, *p0b, *emb1, *p1w, *p1b, *emb2, *p2w, *p2b;
    if (in_sizes[3] == 200*512) {
        emb0 = (const float*)d_in[2]; p0w = (const float*)d_in[3]; p0b = (const float*)d_in[4];
        emb1 = (const float*)d_in[5]; p1w = (const float*)d_in[6]; p1b = (const float*)d_in[7];
        emb2 = (const float*)d_in[8]; p2w = (const float*)d_in[9]; p2b = (const float*)d_in[10];
    } else {
        emb0 = (const float*)d_in[2]; emb1 = (const float*)d_in[3]; emb2 = (const float*)d_in[4];
        p0w = (const float*)d_in[5]; p0b = (const float*)d_in[6];
        p1w = (const float*)d_in[7]; p1b = (const float*)d_in[8];
        p2w = (const float*)d_in[9]; p2b = (const float*)d_in[10];
    }
    const float* keys = (const float*)d_in[11];
    const float* rw   = (const float*)d_in[12];
    const float* rb   = (const float*)d_in[13];
    const float* ew1  = (const float*)d_in[14];
    const float* eb1  = (const float*)d_in[15];
    const float* ew2  = (const float*)d_in[16];
    const float* eb2  = (const float*)d_in[17];
    const float* qkvw = (const float*)d_in[18];
    const float* qkvb = (const float*)d_in[19];
    const float* aow  = (const float*)d_in[20];
    const float* aob  = (const float*)d_in[21];
    const float* l1g  = (const float*)d_in[22];
    const float* l1b  = (const float*)d_in[23];
    const float* l2g  = (const float*)d_in[24];
    const float* l2b  = (const float*)d_in[25];
    const float* f1w  = (const float*)d_in[26];
    const float* f1b  = (const float*)d_in[27];
    const float* f2w  = (const float*)d_in[28];
    const float* f2b  = (const float*)d_in[29];

    float *p_y, *p_part, *p_x, *p_attno, *p_hid;
    __nv_bfloat16 *p_vb, *p_w1i, *p_w2i, *p_hb;
    cudaGetSymbolAddress((void**)&p_y,    g_y);
    cudaGetSymbolAddress((void**)&p_part, g_part);
    cudaGetSymbolAddress((void**)&p_x,    g_x);
    cudaGetSymbolAddress((void**)&p_attno,g_attno);
    cudaGetSymbolAddress((void**)&p_hid,  g_hid);
    cudaGetSymbolAddress((void**)&p_vb,   g_vb);
    cudaGetSymbolAddress((void**)&p_w1i,  g_w1i);
    cudaGetSymbolAddress((void**)&p_w2i,  g_w2i);
    cudaGetSymbolAddress((void**)&p_hb,   g_hb);

    zero_kernel<<<1, 32>>>();
    embed_kernel<<<dim3(TOKENS, 3), 256>>>(Z, emb0, p0w, p0b, emb1, p1w, p1b, emb2, p2w, p2b);
    route_kernel<<<dim3(TOKENS, 3), 256>>>(keys, rw, rb);
    iv_kernel<<<3*TOKENS, 64>>>();
    iw_kernel<<<dim3(HID/32, DM/32, NE), 128>>>(ew1, p_w1i, DM, HID);
    iw_kernel<<<dim3(DM/32, HID/32, NE), 128>>>(ew2, p_w2i, HID, DM);

    // MoE up: K_eff = 3*512 = 1536 -> 48 chunks; N tiles = 2048/64 = 32
    moe_mma_kernel<1, 48, 3*DM, HID><<<dim3(HID/64, 7, NE), 256>>>(
        p_vb, p_w1i, eb1, nullptr, p_hb);
    // MoE down: K_eff = 3*2048 = 6144 -> 192 chunks; N tiles = 512/64 = 8
    moe_mma_kernel<2, 192, 3*HID, DM><<<dim3(DM/64, 7, NE), 256>>>(
        p_hb, p_w2i, eb2, p_y, nullptr);
    combine_kernel<<<TOKENS, DM>>>(frac);

    for (int i = 0; i < 3; i++) {
        dgemm_kernel<4><<<dim3(12, 3, 4), 256>>>(p_x, qkvw + (size_t)i*DM*3*DM, p_part,
                                                 TOKENS, 3*DM, DM);
        attn_kernel<<<dim3(32, 8), 128>>>(p_part, qkvb + (size_t)i*3*DM);
        dgemm_kernel<8><<<dim3(4, 3, 8), 256>>>(p_attno, aow + (size_t)i*DM*DM, p_part,
                                                TOKENS, DM, DM);
        reduce_addln_kernel<<<TOKENS, 256>>>(p_part, 8, aob + (size_t)i*DM, l1g + i*DM, l1b + i*DM);
        dgemm_kernel<4><<<dim3(16, 3, 4), 256>>>(p_x, f1w + (size_t)i*DM*HID, p_part,
                                                 TOKENS, HID, DM);
        reduce_bias_kernel<2><<<(TOKENS*HID + 255)/256, 256>>>(p_part, f1b + (size_t)i*HID,
                                                               p_hid, TOKENS, HID, 4);
        dgemm_kernel<16><<<dim3(4, 3, 16), 256>>>(p_hid, f2w + (size_t)i*HID*DM, p_part,
                                                  TOKENS, DM, HID);
        reduce_addln_kernel<<<TOKENS, 256>>>(p_part, 16, f2b + (size_t)i*DM, l2g + i*DM, l2b + i*DM);
    }
    finalize_kernel<<<TOKENS, DM>>>(frac, (float*)d_out);
}

// round 7
// speedup vs baseline: 1.1349x; 1.1349x over previous
#include <cuda_runtime.h>
#include <math.h>

#define TOKENS 288
#define DM 512
#define NE 16
#define KTOP 4
#define NPAIR (3*TOKENS*KTOP)   // 3456
#define LCAP 1024
#define HID 2048
#define DSPLIT 8

// ---------------- scratch (device globals; allocation-free) ----------------
__device__ float g_views[3*TOKENS*DM];
__device__ float g_pw[NPAIR];
__device__ int   g_counts[NE];
__device__ int   g_lists[NE*LCAP];
__device__ float g_h[(size_t)NPAIR*HID];                 // 28 MB
__device__ float g_ypart[(size_t)DSPLIT*NPAIR*DM];       // 57 MB
__device__ float g_part[(size_t)4*TOKENS*HID];           // qkv / ffn1 partials
__device__ float g_partB[(size_t)16*TOKENS*DM];          // attn_out / ffn2 partials
__device__ float g_x[TOKENS*DM];
__device__ float g_attno[TOKENS*DM];

__global__ void zero_kernel() { if (threadIdx.x < NE) g_counts[threadIdx.x] = 0; }

// ---------------- f32x2 helpers ----------------
__device__ __forceinline__ unsigned long long fma2(unsigned long long a, unsigned long long b,
                                                   unsigned long long c) {
    unsigned long long d;
    asm("fma.rn.f32x2 %0, %1, %2, %3;" : "=l"(d) : "l"(a), "l"(b), "l"(c));
    return d;
}
__device__ __forceinline__ void unpack2(unsigned long long v, float& lo, float& hi) {
    asm("mov.b64 {%0,%1}, %2;" : "=f"(lo), "=f"(hi) : "l"(v));
}

// ---------------- fused embedding + routing: one block per (token, view) ------
__global__ void embed_route_kernel(const int* __restrict__ Z,
    const float* __restrict__ e0, const float* __restrict__ p0, const float* __restrict__ b0,
    const float* __restrict__ e1, const float* __restrict__ p1, const float* __restrict__ b1,
    const float* __restrict__ e2, const float* __restrict__ p2, const float* __restrict__ b2,
    const float* __restrict__ keys, const float* __restrict__ rw, const float* __restrict__ rb)
{
    int t = blockIdx.x, view = blockIdx.y;
    const float *emb, *pw, *pb; int F;
    if (view == 0)      { emb = e0; pw = p0; pb = b0; F = 200; }
    else if (view == 1) { emb = e1; pw = p1; pb = b1; F = 132; }
    else                { emb = e2; pw = p2; pb = b2; F = 112; }
    __shared__ float er[200];
    __shared__ float vs[DM];
    __shared__ float logits[NE];
    int z = Z[t];
    for (int f = threadIdx.x; f < F; f += blockDim.x) er[f] = emb[z*F + f];
    __syncthreads();
    for (int d = threadIdx.x; d < DM; d += blockDim.x) {
        float acc = pb[d];
        for (int f = 0; f < F; f++) acc = fmaf(er[f], pw[f*DM + d], acc);
        vs[d] = acc;
        g_views[(view*TOKENS + t)*DM + d] = acc;
    }
    __syncthreads();
    int warp = threadIdx.x >> 5, lane = threadIdx.x & 31;
    for (int e = warp; e < NE; e += 8) {
        float a = 0.f, b = 0.f;
        for (int d = lane; d < DM; d += 32) {
            float kk = keys[e*DM + d];
            a = fmaf(vs[d], 2.f*kk + rw[(view*DM + d)*NE + e], a);
            b = fmaf(kk, kk, b);
        }
        #pragma unroll
        for (int o = 16; o; o >>= 1) {
            a += __shfl_down_sync(0xffffffffu, a, o);
            b += __shfl_down_sync(0xffffffffu, b, o);
        }
        if (lane == 0) logits[e] = a - b + rb[view*NE + e];
    }
    __syncthreads();
    if (threadIdx.x == 0) {
        float vals[KTOP]; int idx[KTOP]; bool used[NE];
        for (int e = 0; e < NE; e++) used[e] = false;
        for (int k = 0; k < KTOP; k++) {
            float best = -1e30f; int bi = 0;
            for (int e = 0; e < NE; e++)
                if (!used[e] && logits[e] > best) { best = logits[e]; bi = e; }
            used[bi] = true; vals[k] = best; idx[k] = bi;
        }
        float m = vals[0], s = 0.f, w[KTOP];
        for (int k = 0; k < KTOP; k++) { w[k] = expf(vals[k] - m); s += w[k]; }
        float inv = 1.f / s;
        for (int k = 0; k < KTOP; k++) {
            int slot = (view*TOKENS + t)*KTOP + k;
            g_pw[slot] = w[k] * inv;
            int pos = atomicAdd(&g_counts[idx[k]], 1);
            if (pos < LCAP) g_lists[idx[k]*LCAP + pos] = slot;
        }
    }
}

// ---------------- GEMM: 128x128x16 tile, 256 thr, 8x8 micro, duplicated-A smem ----
// A stored as (a,a) float2 pairs -> inner loop issues zero MOVs, FMA2 operands
// come straight from broadcast LDS.64 / LDS.128.
// MODE 0: dense (blockIdx.z = split s; C=[s][M][N] raw partials)
// MODE 1: moe up (blockIdx.z = expert; gather g_views rows via g_lists slot>>2; out g_h[slot]; bias+gelu)
// MODE 2: moe down (blockIdx.z = e*SPLITS+s; gather g_h rows slot; C=[s][NPAIR][N]; bias at s==0)
// AFOLD: A[m][k] = relu(abias[k] + sum_{sp<4} A[sp][m][k])  (folds ffn1 reduce into ffn2)
#define AS_STRIDE 264
template<int MODE, int ACT, int SPLITS, int AFOLD>
__global__ void __launch_bounds__(256, 2) gemm_kernel(
    const float* __restrict__ A, const float* __restrict__ W,
    const float* __restrict__ bias, const float* __restrict__ abias,
    float* __restrict__ C, int M, int N, int K)
{
    int e = 0, s = 0;
    if (MODE == 2)      { e = blockIdx.z / SPLITS; s = blockIdx.z % SPLITS; }
    else if (MODE == 1) { e = blockIdx.z; }
    else                { s = blockIdx.z; }

    int nBase = blockIdx.x * 128, mBase = blockIdx.y * 128;
    int Mcur = M;
    __shared__ int rs[128];
    __shared__ __align__(16) float As[16][AS_STRIDE];   // duplicated pairs: [k][2r],[2r+1]
    __shared__ __align__(16) float Bs[16][128];

    if (MODE != 0) {
        Mcur = g_counts[e];
        if (mBase >= Mcur) return;
        W    += (size_t)e * K * N;
        bias += (size_t)e * N;
        if (threadIdx.x < 128) {
            int gm = mBase + threadIdx.x;
            rs[threadIdx.x] = (gm < Mcur) ? g_lists[e*LCAP + gm] : g_lists[e*LCAP];
        }
        __syncthreads();
    }

    const int tid = threadIdx.x;
    const int tr = tid >> 4, tc = tid & 15;
    const int lr = tid >> 1, lkq = (tid & 1) * 8;
    const int wr = tid >> 4, wc = (tid & 15) * 8;

    const int kChunk = K / SPLITS;
    const int kStart = s * kChunk, kEnd = kStart + kChunk;

    const float* Arow;
    bool rv;
    {
        int gm = mBase + lr;
        rv = gm < Mcur;
        int ar = 0;
        if (rv) {
            if (MODE == 0)      ar = gm;
            else if (MODE == 1) ar = rs[lr] >> 2;
            else                ar = rs[lr];
        }
        Arow = A + (size_t)ar * K;
    }
    const float* Wp = W + nBase + wc;

    unsigned long long acc[8][4];
    #pragma unroll
    for (int i = 0; i < 8; i++)
        #pragma unroll
        for (int j = 0; j < 4; j++) acc[i][j] = 0ull;

    for (int k0 = kStart; k0 < kEnd; k0 += 16) {
        // ---- stage A (duplicated pairs) ----
        float av[8];
        if (!rv) {
            #pragma unroll
            for (int j = 0; j < 8; j++) av[j] = 0.f;
        } else if (AFOLD) {
            #pragma unroll
            for (int h = 0; h < 2; h++) {
                int kk = k0 + lkq + h*4;
                float4 sv = *(const float4*)(abias + kk);
                #pragma unroll
                for (int sp = 0; sp < 4; sp++) {
                    float4 p = *(const float4*)(Arow + (size_t)sp*M*K + kk);
                    sv.x += p.x; sv.y += p.y; sv.z += p.z; sv.w += p.w;
                }
                av[h*4+0] = fmaxf(sv.x, 0.f); av[h*4+1] = fmaxf(sv.y, 0.f);
                av[h*4+2] = fmaxf(sv.z, 0.f); av[h*4+3] = fmaxf(sv.w, 0.f);
            }
        } else {
            float4 a0 = *(const float4*)(Arow + k0 + lkq);
            float4 a1 = *(const float4*)(Arow + k0 + lkq + 4);
            av[0]=a0.x; av[1]=a0.y; av[2]=a0.z; av[3]=a0.w;
            av[4]=a1.x; av[5]=a1.y; av[6]=a1.z; av[7]=a1.w;
        }
        #pragma unroll
        for (int j = 0; j < 8; j++)
            *(float2*)&As[lkq + j][2*lr] = make_float2(av[j], av[j]);
        // ---- stage B ----
        const float* wp = Wp + (size_t)(k0 + wr) * N;
        *(float4*)(&Bs[wr][wc])     = *(const float4*)(wp);
        *(float4*)(&Bs[wr][wc + 4]) = *(const float4*)(wp + 4);
        __syncthreads();
        // ---- compute ----
        #pragma unroll
        for (int k = 0; k < 16; k++) {
            const unsigned long long* ap = (const unsigned long long*)&As[k][0];
            ulonglong2 b0 = *(const ulonglong2*)(&Bs[k][tc*4]);
            ulonglong2 b1 = *(const ulonglong2*)(&Bs[k][64 + tc*4]);
            #pragma unroll
            for (int i = 0; i < 8; i++) {
                unsigned long long a = (i < 4) ? ap[tr*4 + i] : ap[64 + tr*4 + (i-4)];
                acc[i][0] = fma2(a, b0.x, acc[i][0]);
                acc[i][1] = fma2(a, b0.y, acc[i][1]);
                acc[i][2] = fma2(a, b1.x, acc[i][2]);
                acc[i][3] = fma2(a, b1.y, acc[i][3]);
            }
        }
        __syncthreads();
    }

    // ---- epilogue ----
    #pragma unroll
    for (int i = 0; i < 8; i++) {
        int mloc = (i < 4) ? (tr*4 + i) : (64 + tr*4 + (i - 4));
        int m = mBase + mloc;
        if (m >= Mcur) continue;
        size_t crow;
        if (MODE == 0)      crow = ((size_t)s * M + m) * N;
        else if (MODE == 1) crow = (size_t)rs[mloc] * N;
        else                crow = ((size_t)s * NPAIR + rs[mloc]) * N;
        #pragma unroll
        for (int j = 0; j < 4; j++) {
            int n = nBase + ((j < 2) ? (tc*4 + j*2) : (64 + tc*4 + (j - 2)*2));
            float lo, hi; unpack2(acc[i][j], lo, hi);
            if (MODE == 1 || (MODE == 2 && s == 0)) { lo += bias[n]; hi += bias[n+1]; }
            if (ACT == 1) {
                lo = 0.5f*lo*(1.f + erff(lo*0.7071067811865476f));
                hi = 0.5f*hi*(1.f + erff(hi*0.7071067811865476f));
            }
            *(float2*)(C + crow + n) = make_float2(lo, hi);
        }
    }
}

// ---------------- MoE combine + fractional positional encoding ----------------
__global__ void combine_kernel(const float* __restrict__ frac)
{
    int t = blockIdx.x, d = threadIdx.x;
    float acc = 0.f;
    #pragma unroll
    for (int view = 0; view < 3; view++)
        #pragma unroll
        for (int k = 0; k < KTOP; k++) {
            int slot = (view*TOKENS + t)*KTOP + k;
            float y = 0.f;
            #pragma unroll
            for (int s = 0; s < DSPLIT; s++)
                y += g_ypart[((size_t)s * NPAIR + slot)*DM + d];
            acc = fmaf(g_pw[slot], y, acc);
        }
    float fr = frac[t];
    int j; float r;
    if (d < 256) { j = d; r = fr; }
    else {
        j = d - 256;
        float l = log2f(fr);
        r = fminf(0.0025f * l * l, 1.0f);
    }
    r = fmaxf(r, 0.0002f);
    int idx = (int)rintf(r * 5000.0f) - 1;
    idx = max(0, min(4999, idx));
    double dv = pow(50.0, (double)(2*j) / 256.0);
    float pe = (float)((j & 1) ? cos((double)idx / dv) : sin((double)idx / dv));
    g_x[t*DM + d] = acc + pe;
}

// ---------------- attention (folds qkv split-K reduce + bias) ----------------
__global__ void attn_kernel(const float* __restrict__ part, const float* __restrict__ qb)
{
    int b = blockIdx.x, h = blockIdx.y;
    __shared__ float q[9][64], k[9][64], v[9][64], s[9][9];
    for (int i = threadIdx.x; i < 9*64; i += blockDim.x) {
        int l = i >> 6, d = i & 63;
        size_t row = (size_t)(b*9 + l)*1536 + h*64 + d;
        float qq = qb[h*64 + d], kk = qb[512 + h*64 + d], vv = qb[1024 + h*64 + d];
        #pragma unroll
        for (int sp = 0; sp < 4; sp++) {
            size_t o = (size_t)sp*TOKENS*1536 + row;
            qq += part[o]; kk += part[o + 512]; vv += part[o + 1024];
        }
        q[l][d] = qq; k[l][d] = kk; v[l][d] = vv;
    }
    __syncthreads();
    for (int i = threadIdx.x; i < 81; i += blockDim.x) {
        int qi = i / 9, kj = i % 9; float a = 0.f;
        #pragma unroll
        for (int d = 0; d < 64; d++) a = fmaf(q[qi][d], k[kj][d], a);
        s[qi][kj] = a * 0.125f;
    }
    __syncthreads();
    if (threadIdx.x < 9) {
        int i = threadIdx.x;
        float m = s[i][0];
        for (int jj = 1; jj < 9; jj++) m = fmaxf(m, s[i][jj]);
        float sum = 0.f;
        for (int jj = 0; jj < 9; jj++) { float ee = expf(s[i][jj] - m); s[i][jj] = ee; sum += ee; }
        float inv = 1.f / sum;
        for (int jj = 0; jj < 9; jj++) s[i][jj] *= inv;
    }
    __syncthreads();
    for (int i = threadIdx.x; i < 9*64; i += blockDim.x) {
        int l = i >> 6, d = i & 63; float a = 0.f;
        #pragma unroll
        for (int jj = 0; jj < 9; jj++) a = fmaf(s[l][jj], v[jj][d], a);
        g_attno[(size_t)(b*9 + l)*DM + h*64 + d] = a;
    }
}

// ---------------- split-K reduce + residual + LayerNorm ----------------
__device__ __forceinline__ float blockSum(float v, float* red)
{
    int lane = threadIdx.x & 31, w = threadIdx.x >> 5;
    #pragma unroll
    for (int o = 16; o; o >>= 1) v += __shfl_down_sync(0xffffffffu, v, o);
    if (lane == 0) red[w] = v;
    __syncthreads();
    if (threadIdx.x == 0) { float ss = 0.f; for (int i = 0; i < 8; i++) ss += red[i]; red[0] = ss; }
    __syncthreads();
    float r = red[0];
    __syncthreads();
    return r;
}

// fout!=nullptr: last LN -> write fout = ln * frac[t] (and skip g_x update)
__global__ void reduce_addln_kernel(const float* __restrict__ part, int S,
                                    const float* __restrict__ bias,
                                    const float* __restrict__ gam, const float* __restrict__ bet,
                                    float* __restrict__ fout, const float* __restrict__ frac)
{
    int t = blockIdx.x, tid = threadIdx.x;
    __shared__ float red[8];
    float y0 = bias[tid], y1 = bias[tid + 256];
    for (int s = 0; s < S; s++) {
        y0 += part[((size_t)s*TOKENS + t)*DM + tid];
        y1 += part[((size_t)s*TOKENS + t)*DM + tid + 256];
    }
    float s0 = g_x[t*DM + tid] + y0;
    float s1 = g_x[t*DM + tid + 256] + y1;
    float mean = blockSum(s0 + s1, red) * (1.f/512.f);
    float d0 = s0 - mean, d1 = s1 - mean;
    float var = blockSum(d0*d0 + d1*d1, red) * (1.f/512.f);
    float inv = rsqrtf(var + 1e-5f);
    float r0 = d0*inv*gam[tid]       + bet[tid];
    float r1 = d1*inv*gam[tid + 256] + bet[tid + 256];
    if (fout) {
        float fr = frac[t];
        fout[t*DM + tid]       = r0 * fr;
        fout[t*DM + tid + 256] = r1 * fr;
    } else {
        g_x[t*DM + tid]       = r0;
        g_x[t*DM + tid + 256] = r1;
    }
}

// ---------------------------------- host ----------------------------------
extern "C" void kernel_launch(void* const* d_in, const int* in_sizes, int n_in,
                              void* d_out, int out_size)
{
    const int*   Z    = (const int*)d_in[0];
    const float* frac = (const float*)d_in[1];
    const float *emb0, *p0w, *p0b, *emb1, *p1w, *p1b, *emb2, *p2w, *p2b;
    if (in_sizes[3] == 200*512) {
        emb0 = (const float*)d_in[2]; p0w = (const float*)d_in[3]; p0b = (const float*)d_in[4];
        emb1 = (const float*)d_in[5]; p1w = (const float*)d_in[6]; p1b = (const float*)d_in[7];
        emb2 = (const float*)d_in[8]; p2w = (const float*)d_in[9]; p2b = (const float*)d_in[10];
    } else {
        emb0 = (const float*)d_in[2]; emb1 = (const float*)d_in[3]; emb2 = (const float*)d_in[4];
        p0w = (const float*)d_in[5]; p0b = (const float*)d_in[6];
        p1w = (const float*)d_in[7]; p1b = (const float*)d_in[8];
        p2w = (const float*)d_in[9]; p2b = (const float*)d_in[10];
    }
    const float* keys = (const float*)d_in[11];
    const float* rw   = (const float*)d_in[12];
    const float* rb   = (const float*)d_in[13];
    const float* ew1  = (const float*)d_in[14];
    const float* eb1  = (const float*)d_in[15];
    const float* ew2  = (const float*)d_in[16];
    const float* eb2  = (const float*)d_in[17];
    const float* qkvw = (const float*)d_in[18];
    const float* qkvb = (const float*)d_in[19];
    const float* aow  = (const float*)d_in[20];
    const float* aob  = (const float*)d_in[21];
    const float* l1g  = (const float*)d_in[22];
    const float* l1b  = (const float*)d_in[23];
    const float* l2g  = (const float*)d_in[24];
    const float* l2b  = (const float*)d_in[25];
    const float* f1w  = (const float*)d_in[26];
    const float* f1b  = (const float*)d_in[27];
    const float* f2w  = (const float*)d_in[28];
    const float* f2b  = (const float*)d_in[29];

    float *p_views, *p_h, *p_ypart, *p_part, *p_partB, *p_x, *p_attno;
    cudaGetSymbolAddress((void**)&p_views, g_views);
    cudaGetSymbolAddress((void**)&p_h,     g_h);
    cudaGetSymbolAddress((void**)&p_ypart, g_ypart);
    cudaGetSymbolAddress((void**)&p_part,  g_part);
    cudaGetSymbolAddress((void**)&p_partB, g_partB);
    cudaGetSymbolAddress((void**)&p_x,     g_x);
    cudaGetSymbolAddress((void**)&p_attno, g_attno);

    zero_kernel<<<1, 32>>>();
    embed_route_kernel<<<dim3(TOKENS, 3), 256>>>(Z, emb0, p0w, p0b, emb1, p1w, p1b,
                                                 emb2, p2w, p2b, keys, rw, rb);

    // MoE up: gather + bias + gelu, full K=512
    gemm_kernel<1,1,1,0><<<dim3(HID/128, 7, NE), 256>>>(p_views, ew1, eb1, nullptr,
                                                        p_h, 0, HID, DM);
    // MoE down: split-K=8 over K=2048
    gemm_kernel<2,0,DSPLIT,0><<<dim3(DM/128, 7, NE*DSPLIT), 256>>>(p_h, ew2, eb2, nullptr,
                                                                   p_ypart, 0, DM, HID);
    combine_kernel<<<TOKENS, DM>>>(frac);

    for (int i = 0; i < 3; i++) {
        // qkv: split-K=4, partials -> g_part; reduce folded into attn
        gemm_kernel<0,0,4,0><<<dim3(12, 3, 4), 256>>>(p_x, qkvw + (size_t)i*DM*3*DM, nullptr,
                                                      nullptr, p_part, TOKENS, 3*DM, DM);
        attn_kernel<<<dim3(32, 8), 128>>>(p_part, qkvb + (size_t)i*3*DM);
        // attn_out: split-K=8 -> g_partB
        gemm_kernel<0,0,8,0><<<dim3(4, 3, 8), 256>>>(p_attno, aow + (size_t)i*DM*DM, nullptr,
                                                     nullptr, p_partB, TOKENS, DM, DM);
        reduce_addln_kernel<<<TOKENS, 256>>>(p_partB, 8, aob + (size_t)i*DM,
                                             l1g + i*DM, l1b + i*DM, nullptr, nullptr);
        // ffn1: split-K=4, raw partials -> g_part (reduce+relu folded into ffn2 A-loader)
        gemm_kernel<0,0,4,0><<<dim3(16, 3, 4), 256>>>(p_x, f1w + (size_t)i*DM*HID, nullptr,
                                                      nullptr, p_part, TOKENS, HID, DM);
        // ffn2: split-K=16, AFOLD sums ffn1 partials + bias + relu on the fly
        gemm_kernel<0,0,16,1><<<dim3(4, 3, 16), 256>>>(p_part, f2w + (size_t)i*HID*DM, nullptr,
                                                       f1b + (size_t)i*HID, p_partB,
                                                       TOKENS, DM, HID);
        bool last = (i == 2);
        reduce_addln_kernel<<<TOKENS, 256>>>(p_partB, 16, f2b + (size_t)i*DM,
                                             l2g + i*DM, l2b + i*DM,
                                             last ? (float*)d_out : nullptr,
                                             last ? frac : nullptr);
    }
}

// round 8
// speedup vs baseline: 1.2704x; 1.1194x over previous
#include <cuda_runtime.h>
#include <math.h>

#define TOKENS 288
#define DM 512
#define NE 16
#define KTOP 4
#define NPAIR (3*TOKENS*KTOP)   // 3456
#define LCAP 1024
#define HID 2048
#define DSPLIT 8

// ---------------- scratch (device globals; allocation-free) ----------------
__device__ float g_views[3*TOKENS*DM];
__device__ float g_pw[NPAIR];
__device__ int   g_counts[NE];
__device__ int   g_lists[NE*LCAP];
__device__ float g_h[(size_t)NPAIR*HID];                 // 28 MB
__device__ float g_ypart[(size_t)DSPLIT*NPAIR*DM];       // 57 MB
__device__ float g_part[(size_t)16*TOKENS*HID];          // split-K partials
__device__ float g_x[TOKENS*DM];
__device__ float g_attno[TOKENS*DM];
__device__ float g_hid[TOKENS*HID];

__global__ void zero_kernel() { if (threadIdx.x < NE) g_counts[threadIdx.x] = 0; }

// ---------------- f32x2 helpers ----------------
__device__ __forceinline__ unsigned long long dup2(float a) {
    unsigned long long r; asm("mov.b64 %0, {%1,%1};" : "=l"(r) : "f"(a)); return r;
}
__device__ __forceinline__ unsigned long long fma2(unsigned long long a, unsigned long long b,
                                                   unsigned long long c) {
    unsigned long long d;
    asm("fma.rn.f32x2 %0, %1, %2, %3;" : "=l"(d) : "l"(a), "l"(b), "l"(c));
    return d;
}
__device__ __forceinline__ void unpack2(unsigned long long v, float& lo, float& hi) {
    asm("mov.b64 {%0,%1}, %2;" : "=f"(lo), "=f"(hi) : "l"(v));
}

// ---------------- fused embedding + routing ----------------
__global__ void embed_route_kernel(const int* __restrict__ Z,
    const float* __restrict__ e0, const float* __restrict__ p0, const float* __restrict__ b0,
    const float* __restrict__ e1, const float* __restrict__ p1, const float* __restrict__ b1,
    const float* __restrict__ e2, const float* __restrict__ p2, const float* __restrict__ b2,
    const float* __restrict__ keys, const float* __restrict__ rw, const float* __restrict__ rb)
{
    int t = blockIdx.x, view = blockIdx.y;
    const float *emb, *pw, *pb; int F;
    if (view == 0)      { emb = e0; pw = p0; pb = b0; F = 200; }
    else if (view == 1) { emb = e1; pw = p1; pb = b1; F = 132; }
    else                { emb = e2; pw = p2; pb = b2; F = 112; }
    __shared__ float er[200];
    __shared__ float vs[DM];
    __shared__ float logits[NE];
    int z = Z[t];
    for (int f = threadIdx.x; f < F; f += blockDim.x) er[f] = emb[z*F + f];
    __syncthreads();
    for (int d = threadIdx.x; d < DM; d += blockDim.x) {
        float acc = pb[d];
        for (int f = 0; f < F; f++) acc = fmaf(er[f], pw[f*DM + d], acc);
        vs[d] = acc;
        g_views[(view*TOKENS + t)*DM + d] = acc;
    }
    __syncthreads();
    int warp = threadIdx.x >> 5, lane = threadIdx.x & 31;
    for (int e = warp; e < NE; e += 8) {
        float a = 0.f, b = 0.f;
        for (int d = lane; d < DM; d += 32) {
            float kk = keys[e*DM + d];
            a = fmaf(vs[d], 2.f*kk + rw[(view*DM + d)*NE + e], a);
            b = fmaf(kk, kk, b);
        }
        #pragma unroll
        for (int o = 16; o; o >>= 1) {
            a += __shfl_down_sync(0xffffffffu, a, o);
            b += __shfl_down_sync(0xffffffffu, b, o);
        }
        if (lane == 0) logits[e] = a - b + rb[view*NE + e];
    }
    __syncthreads();
    if (threadIdx.x == 0) {
        float vals[KTOP]; int idx[KTOP]; bool used[NE];
        for (int e = 0; e < NE; e++) used[e] = false;
        for (int k = 0; k < KTOP; k++) {
            float best = -1e30f; int bi = 0;
            for (int e = 0; e < NE; e++)
                if (!used[e] && logits[e] > best) { best = logits[e]; bi = e; }
            used[bi] = true; vals[k] = best; idx[k] = bi;
        }
        float m = vals[0], s = 0.f, w[KTOP];
        for (int k = 0; k < KTOP; k++) { w[k] = expf(vals[k] - m); s += w[k]; }
        float inv = 1.f / s;
        for (int k = 0; k < KTOP; k++) {
            int slot = (view*TOKENS + t)*KTOP + k;
            g_pw[slot] = w[k] * inv;
            int pos = atomicAdd(&g_counts[idx[k]], 1);
            if (pos < LCAP) g_lists[idx[k]*LCAP + pos] = slot;
        }
    }
}

// ---------------- GEMM: 64x128x16 tile, 256 thr, 4x8 micro via f32x2 ----------
// Small per-thread footprint (acc = 32 regs) -> 3 CTAs/SM = 24 warps (vs 16).
// MODE 0: dense (blockIdx.z = split s; C=[s][M][N] raw partials)
// MODE 1: moe up (z = expert; gather g_views rows via g_lists slot>>2; out g_h[slot]; bias+gelu)
// MODE 2: moe down (z = e*SPLITS+s; gather g_h rows slot; C=[s][NPAIR][N]; bias at s==0)
#define AS_STRIDE 68
template<int MODE, int ACT, int SPLITS>
__global__ void __launch_bounds__(256, 3) gemm_kernel(
    const float* __restrict__ A, const float* __restrict__ W,
    const float* __restrict__ bias, float* __restrict__ C,
    int M, int N, int K)
{
    int e = 0, s = 0;
    if (MODE == 2)      { e = blockIdx.z / SPLITS; s = blockIdx.z % SPLITS; }
    else if (MODE == 1) { e = blockIdx.z; }
    else                { s = blockIdx.z; }

    int nBase = blockIdx.x * 128, mBase = blockIdx.y * 64;
    int Mcur = M;
    __shared__ int rs[64];
    __shared__ __align__(16) float As[16][AS_STRIDE];
    __shared__ __align__(16) float Bs[16][128];

    if (MODE != 0) {
        Mcur = g_counts[e];
        if (mBase >= Mcur) return;
        W    += (size_t)e * K * N;
        bias += (size_t)e * N;
        if (threadIdx.x < 64) {
            int gm = mBase + threadIdx.x;
            rs[threadIdx.x] = (gm < Mcur) ? g_lists[e*LCAP + gm] : g_lists[e*LCAP];
        }
        __syncthreads();
    }

    const int tid = threadIdx.x;
    const int tr = tid >> 4, tc = tid & 15;        // compute: m-group 0..15, n-col 0..15
    const int lr = tid >> 2, lk4 = (tid & 3) * 4;  // A-load: row 0..63, k-quad
    const int wr = tid >> 4, wc = (tid & 15) * 8;  // B-load

    const int kChunk = K / SPLITS;
    const int kStart = s * kChunk, kEnd = kStart + kChunk;

    const float* Arow;
    bool rv;
    {
        int gm = mBase + lr;
        rv = gm < Mcur;
        int ar = 0;
        if (rv) {
            if (MODE == 0)      ar = gm;
            else if (MODE == 1) ar = rs[lr] >> 2;
            else                ar = rs[lr];
        }
        Arow = A + (size_t)ar * K;
    }
    const float* Wp = W + nBase + wc;

    unsigned long long acc[4][4];
    #pragma unroll
    for (int i = 0; i < 4; i++)
        #pragma unroll
        for (int j = 0; j < 4; j++) acc[i][j] = 0ull;

    for (int k0 = kStart; k0 < kEnd; k0 += 16) {
        float4 av = rv ? *(const float4*)(Arow + k0 + lk4) : make_float4(0,0,0,0);
        As[lk4+0][lr] = av.x; As[lk4+1][lr] = av.y;
        As[lk4+2][lr] = av.z; As[lk4+3][lr] = av.w;
        const float* wp = Wp + (size_t)(k0 + wr) * N;
        *(float4*)(&Bs[wr][wc])     = *(const float4*)(wp);
        *(float4*)(&Bs[wr][wc + 4]) = *(const float4*)(wp + 4);
        __syncthreads();
        #pragma unroll
        for (int k = 0; k < 16; k++) {
            float4 a4 = *(const float4*)(&As[k][tr*4]);
            ulonglong2 b0 = *(const ulonglong2*)(&Bs[k][tc*4]);
            ulonglong2 b1 = *(const ulonglong2*)(&Bs[k][64 + tc*4]);
            unsigned long long da[4];
            da[0] = dup2(a4.x); da[1] = dup2(a4.y); da[2] = dup2(a4.z); da[3] = dup2(a4.w);
            #pragma unroll
            for (int i = 0; i < 4; i++) {
                acc[i][0] = fma2(da[i], b0.x, acc[i][0]);
                acc[i][1] = fma2(da[i], b0.y, acc[i][1]);
                acc[i][2] = fma2(da[i], b1.x, acc[i][2]);
                acc[i][3] = fma2(da[i], b1.y, acc[i][3]);
            }
        }
        __syncthreads();
    }

    #pragma unroll
    for (int i = 0; i < 4; i++) {
        int mloc = tr*4 + i;
        int m = mBase + mloc;
        if (m >= Mcur) continue;
        size_t crow;
        if (MODE == 0)      crow = ((size_t)s * M + m) * N;
        else if (MODE == 1) crow = (size_t)rs[mloc] * N;
        else                crow = ((size_t)s * NPAIR + rs[mloc]) * N;
        #pragma unroll
        for (int j = 0; j < 4; j++) {
            int n = nBase + ((j < 2) ? (tc*4 + j*2) : (64 + tc*4 + (j - 2)*2));
            float lo, hi; unpack2(acc[i][j], lo, hi);
            if (MODE == 1 || (MODE == 2 && s == 0)) { lo += bias[n]; hi += bias[n+1]; }
            if (ACT == 1) {
                lo = 0.5f*lo*(1.f + erff(lo*0.7071067811865476f));
                hi = 0.5f*hi*(1.f + erff(hi*0.7071067811865476f));
            }
            *(float2*)(C + crow + n) = make_float2(lo, hi);
        }
    }
}

// ---------------- split-K reduce + bias (+relu) ----------------
template<int ACT>
__global__ void reduce_bias_kernel(const float* __restrict__ part, const float* __restrict__ bias,
                                   float* __restrict__ out, int M, int N, int S)
{
    int idx = blockIdx.x * 256 + threadIdx.x;
    if (idx >= M * N) return;
    int n = idx % N;
    float acc = bias[n];
    for (int s = 0; s < S; s++) acc += part[(size_t)s * M * N + idx];
    if (ACT == 2) acc = fmaxf(acc, 0.f);
    out[idx] = acc;
}

// ---------------- MoE combine + fractional positional encoding ----------------
__global__ void combine_kernel(const float* __restrict__ frac)
{
    int t = blockIdx.x, d = threadIdx.x;
    float acc = 0.f;
    #pragma unroll
    for (int view = 0; view < 3; view++)
        #pragma unroll
        for (int k = 0; k < KTOP; k++) {
            int slot = (view*TOKENS + t)*KTOP + k;
            float y = 0.f;
            #pragma unroll
            for (int s = 0; s < DSPLIT; s++)
                y += g_ypart[((size_t)s * NPAIR + slot)*DM + d];
            acc = fmaf(g_pw[slot], y, acc);
        }
    float fr = frac[t];
    int j; float r;
    if (d < 256) { j = d; r = fr; }
    else {
        j = d - 256;
        float l = log2f(fr);
        r = fminf(0.0025f * l * l, 1.0f);
    }
    r = fmaxf(r, 0.0002f);
    int idx = (int)rintf(r * 5000.0f) - 1;
    idx = max(0, min(4999, idx));
    double dv = pow(50.0, (double)(2*j) / 256.0);
    float pe = (float)((j & 1) ? cos((double)idx / dv) : sin((double)idx / dv));
    g_x[t*DM + d] = acc + pe;
}

// ---------------- attention (folds qkv split-K reduce + bias) ----------------
__global__ void attn_kernel(const float* __restrict__ part, const float* __restrict__ qb)
{
    int b = blockIdx.x, h = blockIdx.y;
    __shared__ float q[9][64], k[9][64], v[9][64], s[9][9];
    for (int i = threadIdx.x; i < 9*64; i += blockDim.x) {
        int l = i >> 6, d = i & 63;
        size_t row = (size_t)(b*9 + l)*1536 + h*64 + d;
        float qq = qb[h*64 + d], kk = qb[512 + h*64 + d], vv = qb[1024 + h*64 + d];
        #pragma unroll
        for (int sp = 0; sp < 4; sp++) {
            size_t o = (size_t)sp*TOKENS*1536 + row;
            qq += part[o]; kk += part[o + 512]; vv += part[o + 1024];
        }
        q[l][d] = qq; k[l][d] = kk; v[l][d] = vv;
    }
    __syncthreads();
    for (int i = threadIdx.x; i < 81; i += blockDim.x) {
        int qi = i / 9, kj = i % 9; float a = 0.f;
        #pragma unroll
        for (int d = 0; d < 64; d++) a = fmaf(q[qi][d], k[kj][d], a);
        s[qi][kj] = a * 0.125f;
    }
    __syncthreads();
    if (threadIdx.x < 9) {
        int i = threadIdx.x;
        float m = s[i][0];
        for (int jj = 1; jj < 9; jj++) m = fmaxf(m, s[i][jj]);
        float sum = 0.f;
        for (int jj = 0; jj < 9; jj++) { float ee = expf(s[i][jj] - m); s[i][jj] = ee; sum += ee; }
        float inv = 1.f / sum;
        for (int jj = 0; jj < 9; jj++) s[i][jj] *= inv;
    }
    __syncthreads();
    for (int i = threadIdx.x; i < 9*64; i += blockDim.x) {
        int l = i >> 6, d = i & 63; float a = 0.f;
        #pragma unroll
        for (int jj = 0; jj < 9; jj++) a = fmaf(s[l][jj], v[jj][d], a);
        g_attno[(size_t)(b*9 + l)*DM + h*64 + d] = a;
    }
}

// ---------------- split-K reduce + residual + LayerNorm ----------------
__device__ __forceinline__ float blockSum(float v, float* red)
{
    int lane = threadIdx.x & 31, w = threadIdx.x >> 5;
    #pragma unroll
    for (int o = 16; o; o >>= 1) v += __shfl_down_sync(0xffffffffu, v, o);
    if (lane == 0) red[w] = v;
    __syncthreads();
    if (threadIdx.x == 0) { float ss = 0.f; for (int i = 0; i < 8; i++) ss += red[i]; red[0] = ss; }
    __syncthreads();
    float r = red[0];
    __syncthreads();
    return r;
}

__global__ void reduce_addln_kernel(const float* __restrict__ part, int S,
                                    const float* __restrict__ bias,
                                    const float* __restrict__ gam, const float* __restrict__ bet,
                                    float* __restrict__ fout, const float* __restrict__ frac)
{
    int t = blockIdx.x, tid = threadIdx.x;
    __shared__ float red[8];
    float y0 = bias[tid], y1 = bias[tid + 256];
    for (int s = 0; s < S; s++) {
        y0 += part[((size_t)s*TOKENS + t)*DM + tid];
        y1 += part[((size_t)s*TOKENS + t)*DM + tid + 256];
    }
    float s0 = g_x[t*DM + tid] + y0;
    float s1 = g_x[t*DM + tid + 256] + y1;
    float mean = blockSum(s0 + s1, red) * (1.f/512.f);
    float d0 = s0 - mean, d1 = s1 - mean;
    float var = blockSum(d0*d0 + d1*d1, red) * (1.f/512.f);
    float inv = rsqrtf(var + 1e-5f);
    float r0 = d0*inv*gam[tid]       + bet[tid];
    float r1 = d1*inv*gam[tid + 256] + bet[tid + 256];
    if (fout) {
        float fr = frac[t];
        fout[t*DM + tid]       = r0 * fr;
        fout[t*DM + tid + 256] = r1 * fr;
    } else {
        g_x[t*DM + tid]       = r0;
        g_x[t*DM + tid + 256] = r1;
    }
}

// ---------------------------------- host ----------------------------------
extern "C" void kernel_launch(void* const* d_in, const int* in_sizes, int n_in,
                              void* d_out, int out_size)
{
    const int*   Z    = (const int*)d_in[0];
    const float* frac = (const float*)d_in[1];
    const float *emb0, *p0w, *p0b, *emb1, *p1w, *p1b, *emb2, *p2w, *p2b;
    if (in_sizes[3] == 200*512) {
        emb0 = (const float*)d_in[2]; p0w = (const float*)d_in[3]; p0b = (const float*)d_in[4];
        emb1 = (const float*)d_in[5]; p1w = (const float*)d_in[6]; p1b = (const float*)d_in[7];
        emb2 = (const float*)d_in[8]; p2w = (const float*)d_in[9]; p2b = (const float*)d_in[10];
    } else {
        emb0 = (const float*)d_in[2]; emb1 = (const float*)d_in[3]; emb2 = (const float*)d_in[4];
        p0w = (const float*)d_in[5]; p0b = (const float*)d_in[6];
        p1w = (const float*)d_in[7]; p1b = (const float*)d_in[8];
        p2w = (const float*)d_in[9]; p2b = (const float*)d_in[10];
    }
    const float* keys = (const float*)d_in[11];
    const float* rw   = (const float*)d_in[12];
    const float* rb   = (const float*)d_in[13];
    const float* ew1  = (const float*)d_in[14];
    const float* eb1  = (const float*)d_in[15];
    const float* ew2  = (const float*)d_in[16];
    const float* eb2  = (const float*)d_in[17];
    const float* qkvw = (const float*)d_in[18];
    const float* qkvb = (const float*)d_in[19];
    const float* aow  = (const float*)d_in[20];
    const float* aob  = (const float*)d_in[21];
    const float* l1g  = (const float*)d_in[22];
    const float* l1b  = (const float*)d_in[23];
    const float* l2g  = (const float*)d_in[24];
    const float* l2b  = (const float*)d_in[25];
    const float* f1w  = (const float*)d_in[26];
    const float* f1b  = (const float*)d_in[27];
    const float* f2w  = (const float*)d_in[28];
    const float* f2b  = (const float*)d_in[29];

    float *p_views, *p_h, *p_ypart, *p_part, *p_x, *p_attno, *p_hid;
    cudaGetSymbolAddress((void**)&p_views, g_views);
    cudaGetSymbolAddress((void**)&p_h,     g_h);
    cudaGetSymbolAddress((void**)&p_ypart, g_ypart);
    cudaGetSymbolAddress((void**)&p_part,  g_part);
    cudaGetSymbolAddress((void**)&p_x,     g_x);
    cudaGetSymbolAddress((void**)&p_attno, g_attno);
    cudaGetSymbolAddress((void**)&p_hid,   g_hid);

    zero_kernel<<<1, 32>>>();
    embed_route_kernel<<<dim3(TOKENS, 3), 256>>>(Z, emb0, p0w, p0b, emb1, p1w, p1b,
                                                 emb2, p2w, p2b, keys, rw, rb);

    // MoE up: gather + bias + gelu, full K=512.  64-row M tiles: 14 per expert
    gemm_kernel<1,1,1><<<dim3(HID/128, 14, NE), 256>>>(p_views, ew1, eb1, p_h, 0, HID, DM);
    // MoE down: split-K=8 over K=2048
    gemm_kernel<2,0,DSPLIT><<<dim3(DM/128, 14, NE*DSPLIT), 256>>>(p_h, ew2, eb2, p_ypart,
                                                                  0, DM, HID);
    combine_kernel<<<TOKENS, DM>>>(frac);

    for (int i = 0; i < 3; i++) {
        // qkv: [288,512]@[512,1536], split-K=4; reduce folded into attn
        gemm_kernel<0,0,4><<<dim3(12, 5, 4), 256>>>(p_x, qkvw + (size_t)i*DM*3*DM, nullptr,
                                                    p_part, TOKENS, 3*DM, DM);
        attn_kernel<<<dim3(32, 8), 128>>>(p_part, qkvb + (size_t)i*3*DM);
        // attn_out: split-K=8
        gemm_kernel<0,0,8><<<dim3(4, 5, 8), 256>>>(p_attno, aow + (size_t)i*DM*DM, nullptr,
                                                   p_part, TOKENS, DM, DM);
        reduce_addln_kernel<<<TOKENS, 256>>>(p_part, 8, aob + (size_t)i*DM,
                                             l1g + i*DM, l1b + i*DM, nullptr, nullptr);
        // ffn1: split-K=4, reduce+bias+relu -> g_hid
        gemm_kernel<0,0,4><<<dim3(16, 5, 4), 256>>>(p_x, f1w + (size_t)i*DM*HID, nullptr,
                                                    p_part, TOKENS, HID, DM);
        reduce_bias_kernel<2><<<(TOKENS*HID + 255)/256, 256>>>(p_part, f1b + (size_t)i*HID,
                                                               p_hid, TOKENS, HID, 4);
        // ffn2: split-K=16
        gemm_kernel<0,0,16><<<dim3(4, 5, 16), 256>>>(p_hid, f2w + (size_t)i*HID*DM, nullptr,
                                                     p_part, TOKENS, DM, HID);
        bool last = (i == 2);
        reduce_addln_kernel<<<TOKENS, 256>>>(p_part, 16, f2b + (size_t)i*DM,
                                             l2g + i*DM, l2b + i*DM,
                                             last ? (float*)d_out : nullptr,
                                             last ? frac : nullptr);
    }
}